// round 9
// baseline (speedup 1.0000x reference)
#include <cuda_runtime.h>
#include <cuda_bf16.h>
#include <mma.h>
#include <math.h>
#include <stdint.h>

using namespace nvcuda;

#define NN 8192
#define KNB 16
#define DD 256
#define EE 128
#define HH 512
#define OO 256

// ---- scratch (no allocations allowed; __device__ globals) ----
__device__ float g_yn[NN * HH];
__device__ float g_ye[NN * HH];
__device__ float g_wsn[NN * KNB];
__device__ float g_wse[NN * KNB];
__device__ float g_aggn[NN * DD];
__device__ float g_agge[NN * EE];
// bf16 hi/lo splits: big tensors
__device__ __nv_bfloat16 g_nhi[NN * KNB * DD];
__device__ __nv_bfloat16 g_nlo[NN * KNB * DD];
__device__ __nv_bfloat16 g_ehi[NN * KNB * EE];
__device__ __nv_bfloat16 g_elo[NN * KNB * EE];
// chain activations (bf16 hi/lo, written by wgemm SPLITOUT)
__device__ __nv_bfloat16 g_h1hi[NN * HH];
__device__ __nv_bfloat16 g_h1lo[NN * HH];
__device__ __nv_bfloat16 g_xahi[NN * HH];
__device__ __nv_bfloat16 g_xalo[NN * HH];
__device__ __nv_bfloat16 g_xhi[NN * DD];
__device__ __nv_bfloat16 g_xlo[NN * DD];
__device__ __nv_bfloat16 g_anhi[NN * DD];
__device__ __nv_bfloat16 g_anlo[NN * DD];
__device__ __nv_bfloat16 g_aehi[NN * EE];
__device__ __nv_bfloat16 g_aelo[NN * EE];
// weight splits
__device__ __nv_bfloat16 g_w1nhi[HH * DD];
__device__ __nv_bfloat16 g_w1nlo[HH * DD];
__device__ __nv_bfloat16 g_w1ehi[HH * EE];
__device__ __nv_bfloat16 g_w1elo[HH * EE];
__device__ __nv_bfloat16 g_w1xhi[HH * DD];
__device__ __nv_bfloat16 g_w1xlo[HH * DD];
__device__ __nv_bfloat16 g_w2xhi[HH * HH];
__device__ __nv_bfloat16 g_w2xlo[HH * HH];
__device__ __nv_bfloat16 g_w2nhi[HH * HH];
__device__ __nv_bfloat16 g_w2nlo[HH * HH];
__device__ __nv_bfloat16 g_w2ehi[HH * HH];
__device__ __nv_bfloat16 g_w2elo[HH * HH];
__device__ __nv_bfloat16 g_wfxhi[OO * DD];
__device__ __nv_bfloat16 g_wfxlo[OO * DD];
__device__ __nv_bfloat16 g_wfnhi[OO * DD];
__device__ __nv_bfloat16 g_wfnlo[OO * DD];
__device__ __nv_bfloat16 g_wfehi[OO * EE];
__device__ __nv_bfloat16 g_wfelo[OO * EE];

// ============================================================
// fp32 -> bf16 hi/lo split (elementwise, float4-vectorized)
// ============================================================
__global__ void __launch_bounds__(256)
split_kernel(const float* __restrict__ src, __nv_bfloat16* __restrict__ hi,
             __nv_bfloat16* __restrict__ lo, int n4)
{
    int i = blockIdx.x * blockDim.x + threadIdx.x;
    if (i >= n4) return;
    float4 v = ((const float4*)src)[i];
    __nv_bfloat162 h01 = __floats2bfloat162_rn(v.x, v.y);
    __nv_bfloat162 h23 = __floats2bfloat162_rn(v.z, v.w);
    float rx = v.x - __bfloat162float(h01.x);
    float ry = v.y - __bfloat162float(h01.y);
    float rz = v.z - __bfloat162float(h23.x);
    float rw = v.w - __bfloat162float(h23.y);
    __nv_bfloat162 l01 = __floats2bfloat162_rn(rx, ry);
    __nv_bfloat162 l23 = __floats2bfloat162_rn(rz, rw);
    uint2 ho, loo;
    ho.x  = *(uint32_t*)&h01; ho.y  = *(uint32_t*)&h23;
    loo.x = *(uint32_t*)&l01; loo.y = *(uint32_t*)&l23;
    ((uint2*)hi)[i] = ho;
    ((uint2*)lo)[i] = loo;
}

// ============================================================
// B-fragment selector: BT=true -> B is [N,K] K-major (col_major frag),
//                      BT=false -> B is [K,N] N-major (row_major frag)
// ============================================================
template<bool BT> struct BFrag;
template<> struct BFrag<true> {
    using T = wmma::fragment<wmma::matrix_b, 16, 16, 16, __nv_bfloat16, wmma::col_major>;
    static __device__ __forceinline__ void load(T& f, const __nv_bfloat16* base,
                                                int n_idx, int ks) {
        wmma::load_matrix_sync(f, base + n_idx * 72 + ks * 16, 72);
    }
};
template<> struct BFrag<false> {
    using T = wmma::fragment<wmma::matrix_b, 16, 16, 16, __nv_bfloat16, wmma::row_major>;
    static __device__ __forceinline__ void load(T& f, const __nv_bfloat16* base,
                                                int n_idx, int ks) {
        wmma::load_matrix_sync(f, base + (ks * 16) * 72 + n_idx, 72);
    }
};

// ============================================================
// Generic WMMA GEMM, bf16 hi/lo 3-term (~fp32 accuracy):
//   C[M,Nc] = act( A[M,Kc] @ op(B) )
// Tile 128x64, 8 warps = 4(M) x 2(N), warp 32x32, K staged 64-wide.
// SPLITOUT: write hi/lo bf16 (for chained GEMMs). Else fp32 (+bias/relu).
// M = 8192 fixed (grid.y = 64); Nc % 64 == 0; Kc % 64 == 0.
// ============================================================
// dyn smem: As_hi 128x72 (18432) | As_lo (18432) | Bs_hi 64x72 (9216) | Bs_lo (9216)
// Ds 128x68 fp32 (34816) unions with As region.
#define WG_SMEM 55296

template<bool BT, bool TANH_, bool BIASRELU_, bool SPLITOUT>
__global__ void __launch_bounds__(256, 2)
wgemm(const __nv_bfloat16* __restrict__ Ahi, const __nv_bfloat16* __restrict__ Alo,
      const __nv_bfloat16* __restrict__ Bhi, const __nv_bfloat16* __restrict__ Blo,
      const float* __restrict__ bias,
      float* __restrict__ Cf, __nv_bfloat16* __restrict__ Chi, __nv_bfloat16* __restrict__ Clo,
      int Nc, int Kc, int ldc, int coff)
{
    extern __shared__ char sm[];
    __nv_bfloat16* As_hi = (__nv_bfloat16*)(sm);
    __nv_bfloat16* As_lo = (__nv_bfloat16*)(sm + 18432);
    __nv_bfloat16* Bs_hi = (__nv_bfloat16*)(sm + 36864);
    __nv_bfloat16* Bs_lo = (__nv_bfloat16*)(sm + 46080);
    float* Ds = (float*)sm;

    const int tid = threadIdx.x;
    const int wid = tid >> 5;
    const int m0 = blockIdx.y * 128;
    const int n0 = blockIdx.x * 64;
    const int m_off = (wid & 3) * 32;
    const int n_off = (wid >> 2) * 32;

    wmma::fragment<wmma::accumulator, 16, 16, 16, float> acc[2][2];
    #pragma unroll
    for (int mi = 0; mi < 2; mi++)
        #pragma unroll
        for (int ni = 0; ni < 2; ni++)
            wmma::fill_fragment(acc[mi][ni], 0.0f);

    const int KCH = Kc >> 6;
    for (int kc = 0; kc < KCH; kc++) {
        __syncthreads();
        // stage A 128x64 hi/lo
        #pragma unroll
        for (int i = 0; i < 4; i++) {
            int g = tid + i * 256;
            int row = g >> 3, c8 = (g & 7) * 8;
            size_t soff = (size_t)(m0 + row) * Kc + kc * 64 + c8;
            *(int4*)(As_hi + row * 72 + c8) = *(const int4*)(Ahi + soff);
            *(int4*)(As_lo + row * 72 + c8) = *(const int4*)(Alo + soff);
        }
        // stage B 64x64 hi/lo
        #pragma unroll
        for (int i = 0; i < 2; i++) {
            int g = tid + i * 256;
            int row = g >> 3, c8 = (g & 7) * 8;
            size_t soff;
            if (BT) soff = (size_t)(n0 + row) * Kc + kc * 64 + c8;   // row = n
            else    soff = (size_t)(kc * 64 + row) * Nc + n0 + c8;   // row = k
            *(int4*)(Bs_hi + row * 72 + c8) = *(const int4*)(Bhi + soff);
            *(int4*)(Bs_lo + row * 72 + c8) = *(const int4*)(Blo + soff);
        }
        __syncthreads();

        #pragma unroll
        for (int ks = 0; ks < 4; ks++) {
            wmma::fragment<wmma::matrix_a, 16, 16, 16, __nv_bfloat16, wmma::row_major> ah[2], al[2];
            typename BFrag<BT>::T bh[2], bl[2];
            #pragma unroll
            for (int mi = 0; mi < 2; mi++) {
                wmma::load_matrix_sync(ah[mi], As_hi + (m_off + 16 * mi) * 72 + ks * 16, 72);
                wmma::load_matrix_sync(al[mi], As_lo + (m_off + 16 * mi) * 72 + ks * 16, 72);
            }
            #pragma unroll
            for (int ni = 0; ni < 2; ni++) {
                BFrag<BT>::load(bh[ni], Bs_hi, n_off + 16 * ni, ks);
                BFrag<BT>::load(bl[ni], Bs_lo, n_off + 16 * ni, ks);
            }
            #pragma unroll
            for (int mi = 0; mi < 2; mi++)
                #pragma unroll
                for (int ni = 0; ni < 2; ni++) {
                    wmma::mma_sync(acc[mi][ni], ah[mi], bh[ni], acc[mi][ni]);
                    wmma::mma_sync(acc[mi][ni], ah[mi], bl[ni], acc[mi][ni]);
                    wmma::mma_sync(acc[mi][ni], al[mi], bh[ni], acc[mi][ni]);
                }
        }
    }

    // epilogue via smem
    __syncthreads();
    #pragma unroll
    for (int mi = 0; mi < 2; mi++)
        #pragma unroll
        for (int ni = 0; ni < 2; ni++)
            wmma::store_matrix_sync(Ds + (m_off + 16 * mi) * 68 + n_off + 16 * ni,
                                    acc[mi][ni], 68, wmma::mem_row_major);
    __syncthreads();

    const int r = tid >> 1, ch = (tid & 1) * 32;
    const float* drow = Ds + r * 68 + ch;
    if (SPLITOUT) {
        #pragma unroll
        for (int j4 = 0; j4 < 4; j4++) {
            float v[8];
            #pragma unroll
            for (int jj = 0; jj < 8; jj++) {
                float t = drow[j4 * 8 + jj];
                v[jj] = TANH_ ? tanhf(t) : t;
            }
            uint4 ho, lo;
            uint32_t* hp = (uint32_t*)&ho;
            uint32_t* lp = (uint32_t*)&lo;
            #pragma unroll
            for (int p = 0; p < 4; p++) {
                __nv_bfloat162 h = __floats2bfloat162_rn(v[2 * p], v[2 * p + 1]);
                float r0 = v[2 * p]     - __bfloat162float(h.x);
                float r1 = v[2 * p + 1] - __bfloat162float(h.y);
                __nv_bfloat162 l = __floats2bfloat162_rn(r0, r1);
                hp[p] = *(uint32_t*)&h;
                lp[p] = *(uint32_t*)&l;
            }
            size_t o = (size_t)(m0 + r) * ldc + coff + n0 + ch + j4 * 8;
            *(uint4*)(Chi + o) = ho;
            *(uint4*)(Clo + o) = lo;
        }
    } else {
        #pragma unroll
        for (int jv = 0; jv < 8; jv++) {
            float4 vv;
            float* vp = (float*)&vv;
            #pragma unroll
            for (int j = 0; j < 4; j++) {
                int col = ch + jv * 4 + j;
                float val = drow[jv * 4 + j];
                if (TANH_) val = tanhf(val);
                if (BIASRELU_) { val += bias[n0 + col]; val = fmaxf(val, 0.0f); }
                vp[j] = val;
            }
            *(float4*)(Cf + (size_t)(m0 + r) * ldc + coff + n0 + ch + jv * 4) = vv;
        }
    }
}

// ============================================================
// Tensor-core fused logit kernel (UNCHANGED from passing R8)
// ============================================================
#define WS2_SMEM 71680

template<int KD>
__global__ void __launch_bounds__(256, 2)
ws_mma(const __nv_bfloat16* __restrict__ Ahi, const __nv_bfloat16* __restrict__ Alo,
       const __nv_bfloat16* __restrict__ Whi, const __nv_bfloat16* __restrict__ Wlo,
       const float* __restrict__ y, float* __restrict__ ws)
{
    extern __shared__ char sm[];
    constexpr int KCH = KD / 64;

    __nv_bfloat16* As_hi = (__nv_bfloat16*)(sm);
    __nv_bfloat16* As_lo = (__nv_bfloat16*)(sm + 18432);
    __nv_bfloat16* Bs_hi = (__nv_bfloat16*)(sm + 36864);
    __nv_bfloat16* Bs_lo = (__nv_bfloat16*)(sm + 46080);
    float* Ds = (float*)sm;
    float* ys = (float*)(sm + 55296);

    const int tid = threadIdx.x;
    const int wid = tid >> 5;
    const int m0 = blockIdx.x * 128;
    const int node0 = m0 >> 4;
    const int m_off = (wid & 3) * 32;
    const int n_off = (wid >> 2) * 32;

    {
        const float4* src = (const float4*)(y + (size_t)node0 * HH);
        #pragma unroll
        for (int i = 0; i < 4; i++)
            ((float4*)ys)[tid + i * 256] = src[tid + i * 256];
    }

    float wsacc = 0.0f;

    for (int hc = 0; hc < 8; hc++) {
        wmma::fragment<wmma::accumulator, 16, 16, 16, float> acc[2][2];
        #pragma unroll
        for (int mi = 0; mi < 2; mi++)
            #pragma unroll
            for (int ni = 0; ni < 2; ni++)
                wmma::fill_fragment(acc[mi][ni], 0.0f);

        for (int kc = 0; kc < KCH; kc++) {
            __syncthreads();
            #pragma unroll
            for (int i = 0; i < 4; i++) {
                int g = tid + i * 256;
                int row = g >> 3, c8 = (g & 7) * 8;
                size_t soff = (size_t)(m0 + row) * KD + kc * 64 + c8;
                *(int4*)(As_hi + row * 72 + c8) = *(const int4*)(Ahi + soff);
                *(int4*)(As_lo + row * 72 + c8) = *(const int4*)(Alo + soff);
            }
            #pragma unroll
            for (int i = 0; i < 2; i++) {
                int g = tid + i * 256;
                int row = g >> 3, c8 = (g & 7) * 8;
                size_t soff = (size_t)(hc * 64 + row) * KD + kc * 64 + c8;
                *(int4*)(Bs_hi + row * 72 + c8) = *(const int4*)(Whi + soff);
                *(int4*)(Bs_lo + row * 72 + c8) = *(const int4*)(Wlo + soff);
            }
            __syncthreads();

            #pragma unroll
            for (int ks = 0; ks < 4; ks++) {
                wmma::fragment<wmma::matrix_a, 16, 16, 16, __nv_bfloat16, wmma::row_major> ah[2], al[2];
                wmma::fragment<wmma::matrix_b, 16, 16, 16, __nv_bfloat16, wmma::col_major> bh[2], bl[2];
                #pragma unroll
                for (int mi = 0; mi < 2; mi++) {
                    wmma::load_matrix_sync(ah[mi], As_hi + (m_off + 16 * mi) * 72 + ks * 16, 72);
                    wmma::load_matrix_sync(al[mi], As_lo + (m_off + 16 * mi) * 72 + ks * 16, 72);
                }
                #pragma unroll
                for (int ni = 0; ni < 2; ni++) {
                    wmma::load_matrix_sync(bh[ni], Bs_hi + (n_off + 16 * ni) * 72 + ks * 16, 72);
                    wmma::load_matrix_sync(bl[ni], Bs_lo + (n_off + 16 * ni) * 72 + ks * 16, 72);
                }
                #pragma unroll
                for (int mi = 0; mi < 2; mi++)
                    #pragma unroll
                    for (int ni = 0; ni < 2; ni++) {
                        wmma::mma_sync(acc[mi][ni], ah[mi], bh[ni], acc[mi][ni]);
                        wmma::mma_sync(acc[mi][ni], ah[mi], bl[ni], acc[mi][ni]);
                        wmma::mma_sync(acc[mi][ni], al[mi], bh[ni], acc[mi][ni]);
                    }
            }
        }

        __syncthreads();
        #pragma unroll
        for (int mi = 0; mi < 2; mi++)
            #pragma unroll
            for (int ni = 0; ni < 2; ni++)
                wmma::store_matrix_sync(Ds + (m_off + 16 * mi) * 68 + n_off + 16 * ni,
                                        acc[mi][ni], 68, wmma::mem_row_major);
        __syncthreads();
        {
            int r = tid >> 1, ch = (tid & 1) * 32;
            const float* drow = Ds + r * 68 + ch;
            const float* yrow = ys + (r >> 4) * HH + hc * 64 + ch;
            float p = 0.0f;
            #pragma unroll
            for (int j = 0; j < 32; j++)
                p = fmaf(tanhf(drow[j]), yrow[j], p);
            wsacc += p;
        }
    }

    float other = __shfl_xor_sync(0xffffffffu, wsacc, 1);
    if ((tid & 1) == 0)
        ws[m0 + (tid >> 1)] = wsacc + other;
}

// ============================================================
// Softmax (scaled / masked) + weighted aggregation (unchanged)
// ============================================================
__global__ void __launch_bounds__(128)
softmax_agg(const float* __restrict__ wsn, const float* __restrict__ wse,
            const int* __restrict__ mask, const float* __restrict__ neibs,
            const float* __restrict__ edges,
            float* __restrict__ aggn, float* __restrict__ agge)
{
    const int n = blockIdx.x;
    const int tid = threadIdx.x;
    __shared__ float s1[16], s2[16];
    if (tid < 16) {
        s1[tid] = wsn[n * 16 + tid] * 0.04419417382415922f;  // 1/sqrt(512)
        s2[tid] = wse[n * 16 + tid] - 9999999.0f * (float)mask[n * 16 + tid];
    }
    __syncthreads();

    float w1[16], w2[16];
    float m1 = -1e30f, m2 = -1e30f;
    #pragma unroll
    for (int k = 0; k < 16; k++) {
        m1 = fmaxf(m1, s1[k]);
        m2 = fmaxf(m2, s2[k]);
    }
    float t1 = 0.0f, t2 = 0.0f;
    #pragma unroll
    for (int k = 0; k < 16; k++) {
        w1[k] = expf(s1[k] - m1); t1 += w1[k];
        w2[k] = expf(s2[k] - m2); t2 += w2[k];
    }
    const float r1 = 1.0f / t1, r2 = 1.0f / t2;

    #pragma unroll
    for (int p = 0; p < 2; p++) {
        int d = tid + p * 128;
        float acc = 0.0f;
        #pragma unroll
        for (int k = 0; k < 16; k++)
            acc = fmaf(w1[k], neibs[((size_t)n * 16 + k) * DD + d], acc);
        aggn[(size_t)n * DD + d] = acc * r1;
    }
    {
        int d = tid;
        float acc = 0.0f;
        #pragma unroll
        for (int k = 0; k < 16; k++)
            acc = fmaf(w2[k], edges[((size_t)n * 16 + k) * EE + d], acc);
        agge[(size_t)n * EE + d] = acc * r2;
    }
}

// ============================================================
extern "C" void kernel_launch(void* const* d_in, const int* in_sizes, int n_in,
                              void* d_out, int out_size)
{
    const float* x     = (const float*)d_in[0];
    const float* neibs = (const float*)d_in[1];
    const float* edge  = (const float*)d_in[2];
    const int*   mask  = (const int*)  d_in[3];
    const float* W1x   = (const float*)d_in[4];
    const float* W2x   = (const float*)d_in[5];
    const float* W1n   = (const float*)d_in[6];
    const float* W2n   = (const float*)d_in[7];
    const float* W1e   = (const float*)d_in[8];
    const float* W2e   = (const float*)d_in[9];
    const float* Wfx   = (const float*)d_in[10];
    const float* bfx   = (const float*)d_in[11];
    const float* Wfn   = (const float*)d_in[12];
    const float* bfn   = (const float*)d_in[13];
    const float* Wfe   = (const float*)d_in[14];
    const float* bfe   = (const float*)d_in[15];
    float* out = (float*)d_out;

    float *yn, *ye, *wsn, *wse, *aggn, *agge;
    cudaGetSymbolAddress((void**)&yn,   g_yn);
    cudaGetSymbolAddress((void**)&ye,   g_ye);
    cudaGetSymbolAddress((void**)&wsn,  g_wsn);
    cudaGetSymbolAddress((void**)&wse,  g_wse);
    cudaGetSymbolAddress((void**)&aggn, g_aggn);
    cudaGetSymbolAddress((void**)&agge, g_agge);

    __nv_bfloat16 *nhi, *nlo, *ehi, *elo, *h1hi, *h1lo, *xahi, *xalo, *xhi, *xlo;
    __nv_bfloat16 *anhi, *anlo, *aehi, *aelo;
    __nv_bfloat16 *w1nhi, *w1nlo, *w1ehi, *w1elo, *w1xhi, *w1xlo;
    __nv_bfloat16 *w2xhi, *w2xlo, *w2nhi, *w2nlo, *w2ehi, *w2elo;
    __nv_bfloat16 *wfxhi, *wfxlo, *wfnhi, *wfnlo, *wfehi, *wfelo;
    cudaGetSymbolAddress((void**)&nhi,   g_nhi);
    cudaGetSymbolAddress((void**)&nlo,   g_nlo);
    cudaGetSymbolAddress((void**)&ehi,   g_ehi);
    cudaGetSymbolAddress((void**)&elo,   g_elo);
    cudaGetSymbolAddress((void**)&h1hi,  g_h1hi);
    cudaGetSymbolAddress((void**)&h1lo,  g_h1lo);
    cudaGetSymbolAddress((void**)&xahi,  g_xahi);
    cudaGetSymbolAddress((void**)&xalo,  g_xalo);
    cudaGetSymbolAddress((void**)&xhi,   g_xhi);
    cudaGetSymbolAddress((void**)&xlo,   g_xlo);
    cudaGetSymbolAddress((void**)&anhi,  g_anhi);
    cudaGetSymbolAddress((void**)&anlo,  g_anlo);
    cudaGetSymbolAddress((void**)&aehi,  g_aehi);
    cudaGetSymbolAddress((void**)&aelo,  g_aelo);
    cudaGetSymbolAddress((void**)&w1nhi, g_w1nhi);
    cudaGetSymbolAddress((void**)&w1nlo, g_w1nlo);
    cudaGetSymbolAddress((void**)&w1ehi, g_w1ehi);
    cudaGetSymbolAddress((void**)&w1elo, g_w1elo);
    cudaGetSymbolAddress((void**)&w1xhi, g_w1xhi);
    cudaGetSymbolAddress((void**)&w1xlo, g_w1xlo);
    cudaGetSymbolAddress((void**)&w2xhi, g_w2xhi);
    cudaGetSymbolAddress((void**)&w2xlo, g_w2xlo);
    cudaGetSymbolAddress((void**)&w2nhi, g_w2nhi);
    cudaGetSymbolAddress((void**)&w2nlo, g_w2nlo);
    cudaGetSymbolAddress((void**)&w2ehi, g_w2ehi);
    cudaGetSymbolAddress((void**)&w2elo, g_w2elo);
    cudaGetSymbolAddress((void**)&wfxhi, g_wfxhi);
    cudaGetSymbolAddress((void**)&wfxlo, g_wfxlo);
    cudaGetSymbolAddress((void**)&wfnhi, g_wfnhi);
    cudaGetSymbolAddress((void**)&wfnlo, g_wfnlo);
    cudaGetSymbolAddress((void**)&wfehi, g_wfehi);
    cudaGetSymbolAddress((void**)&wfelo, g_wfelo);

    // smem attributes
    cudaFuncSetAttribute(ws_mma<DD>, cudaFuncAttributeMaxDynamicSharedMemorySize, WS2_SMEM);
    cudaFuncSetAttribute(ws_mma<EE>, cudaFuncAttributeMaxDynamicSharedMemorySize, WS2_SMEM);
    cudaFuncSetAttribute(wgemm<true,  true,  false, true >, cudaFuncAttributeMaxDynamicSharedMemorySize, WG_SMEM);
    cudaFuncSetAttribute(wgemm<true,  false, false, true >, cudaFuncAttributeMaxDynamicSharedMemorySize, WG_SMEM);
    cudaFuncSetAttribute(wgemm<false, false, false, false>, cudaFuncAttributeMaxDynamicSharedMemorySize, WG_SMEM);
    cudaFuncSetAttribute(wgemm<true,  false, true,  false>, cudaFuncAttributeMaxDynamicSharedMemorySize, WG_SMEM);

    dim3 blk(256);

    // ---- splits for the x_att chain ----
    split_kernel<<<(NN*DD/4 + 255)/256, blk>>>(x,   xhi,   xlo,   NN*DD/4);
    split_kernel<<<(HH*DD/4 + 255)/256, blk>>>(W1x, w1xhi, w1xlo, HH*DD/4);
    split_kernel<<<(HH*HH/4 + 255)/256, blk>>>(W2x, w2xhi, w2xlo, HH*HH/4);
    split_kernel<<<(HH*HH/4 + 255)/256, blk>>>(W2n, w2nhi, w2nlo, HH*HH/4);
    split_kernel<<<(HH*HH/4 + 255)/256, blk>>>(W2e, w2ehi, w2elo, HH*HH/4);

    // ---- x_att chain on tensor cores ----
    // h1 = tanh(x @ W1x^T), split-out
    wgemm<true, true, false, true><<<dim3(HH/64, NN/128), blk, WG_SMEM>>>(
        xhi, xlo, w1xhi, w1xlo, nullptr, nullptr, h1hi, h1lo, HH, DD, HH, 0);
    // xatt = h1 @ W2x^T, split-out
    wgemm<true, false, false, true><<<dim3(HH/64, NN/128), blk, WG_SMEM>>>(
        h1hi, h1lo, w2xhi, w2xlo, nullptr, nullptr, xahi, xalo, HH, HH, HH, 0);
    // yn = xatt @ W2n (B not transposed), fp32 out
    wgemm<false, false, false, false><<<dim3(HH/64, NN/128), blk, WG_SMEM>>>(
        xahi, xalo, w2nhi, w2nlo, nullptr, yn, nullptr, nullptr, HH, HH, HH, 0);
    // ye = xatt @ W2e
    wgemm<false, false, false, false><<<dim3(HH/64, NN/128), blk, WG_SMEM>>>(
        xahi, xalo, w2ehi, w2elo, nullptr, ye, nullptr, nullptr, HH, HH, HH, 0);

    // ---- splits for ws kernels ----
    split_kernel<<<(NN*KNB*DD/4 + 255)/256, blk>>>(neibs, nhi, nlo, NN*KNB*DD/4);
    split_kernel<<<(NN*KNB*EE/4 + 255)/256, blk>>>(edge,  ehi, elo, NN*KNB*EE/4);
    split_kernel<<<(HH*DD/4 + 255)/256, blk>>>(W1n, w1nhi, w1nlo, HH*DD/4);
    split_kernel<<<(HH*EE/4 + 255)/256, blk>>>(W1e, w1ehi, w1elo, HH*EE/4);

    // ---- attention logits (tensor cores, unchanged) ----
    ws_mma<DD><<<(NN * KNB) / 128, blk, WS2_SMEM>>>(nhi, nlo, w1nhi, w1nlo, yn, wsn);
    ws_mma<EE><<<(NN * KNB) / 128, blk, WS2_SMEM>>>(ehi, elo, w1ehi, w1elo, ye, wse);

    // ---- softmax + aggregation ----
    softmax_agg<<<NN, 128>>>(wsn, wse, mask, neibs, edge, aggn, agge);

    // ---- output GEMMs on tensor cores ----
    split_kernel<<<(NN*DD/4 + 255)/256, blk>>>(aggn, anhi, anlo, NN*DD/4);
    split_kernel<<<(NN*EE/4 + 255)/256, blk>>>(agge, aehi, aelo, NN*EE/4);
    split_kernel<<<(OO*DD/4 + 255)/256, blk>>>(Wfx, wfxhi, wfxlo, OO*DD/4);
    split_kernel<<<(OO*DD/4 + 255)/256, blk>>>(Wfn, wfnhi, wfnlo, OO*DD/4);
    split_kernel<<<(OO*EE/4 + 255)/256, blk>>>(Wfe, wfehi, wfelo, OO*EE/4);

    wgemm<true, false, true, false><<<dim3(OO/64, NN/128), blk, WG_SMEM>>>(
        xhi, xlo, wfxhi, wfxlo, bfx, out, nullptr, nullptr, OO, DD, 3*OO, 0);
    wgemm<true, false, true, false><<<dim3(OO/64, NN/128), blk, WG_SMEM>>>(
        anhi, anlo, wfnhi, wfnlo, bfn, out, nullptr, nullptr, OO, DD, 3*OO, OO);
    wgemm<true, false, true, false><<<dim3(OO/64, NN/128), blk, WG_SMEM>>>(
        aehi, aelo, wfehi, wfelo, bfe, out, nullptr, nullptr, OO, EE, 3*OO, 2*OO);
}

// round 10
// speedup vs baseline: 1.3250x; 1.3250x over previous
#include <cuda_runtime.h>
#include <cuda_bf16.h>
#include <mma.h>
#include <math.h>
#include <stdint.h>

using namespace nvcuda;

#define NN 8192
#define KNB 16
#define DD 256
#define EE 128
#define HH 512
#define OO 256

// ---- scratch (no allocations allowed; __device__ globals) ----
__device__ float g_h1[NN * HH];
__device__ float g_xatt[NN * HH];
__device__ float g_yn[NN * HH];
__device__ float g_ye[NN * HH];
__device__ float g_wsn[NN * KNB];
__device__ float g_wse[NN * KNB];
__device__ float g_aggn[NN * DD];
__device__ float g_agge[NN * EE];
// bf16 hi/lo splits
__device__ __nv_bfloat16 g_nhi[NN * KNB * DD];
__device__ __nv_bfloat16 g_nlo[NN * KNB * DD];
__device__ __nv_bfloat16 g_ehi[NN * KNB * EE];
__device__ __nv_bfloat16 g_elo[NN * KNB * EE];
__device__ __nv_bfloat16 g_w1nhi[HH * DD];
__device__ __nv_bfloat16 g_w1nlo[HH * DD];
__device__ __nv_bfloat16 g_w1ehi[HH * EE];
__device__ __nv_bfloat16 g_w1elo[HH * EE];

// ============================================================
// fp32 -> bf16 hi/lo split (elementwise, float4-vectorized)
// ============================================================
__global__ void __launch_bounds__(256)
split_kernel(const float* __restrict__ src, __nv_bfloat16* __restrict__ hi,
             __nv_bfloat16* __restrict__ lo, int n4)
{
    int i = blockIdx.x * blockDim.x + threadIdx.x;
    if (i >= n4) return;
    float4 v = ((const float4*)src)[i];
    __nv_bfloat162 h01 = __floats2bfloat162_rn(v.x, v.y);
    __nv_bfloat162 h23 = __floats2bfloat162_rn(v.z, v.w);
    float rx = v.x - __bfloat162float(h01.x);
    float ry = v.y - __bfloat162float(h01.y);
    float rz = v.z - __bfloat162float(h23.x);
    float rw = v.w - __bfloat162float(h23.y);
    __nv_bfloat162 l01 = __floats2bfloat162_rn(rx, ry);
    __nv_bfloat162 l23 = __floats2bfloat162_rn(rz, rw);
    uint2 ho, loo;
    ho.x  = *(uint32_t*)&h01; ho.y  = *(uint32_t*)&h23;
    loo.x = *(uint32_t*)&l01; loo.y = *(uint32_t*)&l23;
    ((uint2*)hi)[i] = ho;
    ((uint2*)lo)[i] = loo;
}

// ============================================================
// Tensor-core fused logit kernel (mma.sync, bf16 hi/lo 3-term)
//   ws[m] = sum_h tanh( A[m,:] . W1[h,:] ) * y[m/16, h]
// Block: 128 A-rows; H in 4 chunks of 128 (A re-staging halved vs R8);
// 8 warps = 2(M) x 4(N); warp tile 64x32 = 4x2 m16n16k16 fragments.
// ============================================================
// dyn smem:
//   [0]      As_hi 128x72 bf16 (18432)  } union with Ds 128x132 fp32 (67584)
//   [18432]  As_lo (18432)              }
//   [36864]  Bs_hi 128x72 bf16 (18432)  }
//   [55296]  Bs_lo (18432)              }
//   [73728]  ys 8x512 fp32 (16384)
#define WS3_SMEM 90112

template<int KD>
__global__ void __launch_bounds__(256, 2)
ws_mma(const __nv_bfloat16* __restrict__ Ahi, const __nv_bfloat16* __restrict__ Alo,
       const __nv_bfloat16* __restrict__ Whi, const __nv_bfloat16* __restrict__ Wlo,
       const float* __restrict__ y, float* __restrict__ ws)
{
    extern __shared__ char sm[];
    constexpr int KCH = KD / 64;

    __nv_bfloat16* As_hi = (__nv_bfloat16*)(sm);
    __nv_bfloat16* As_lo = (__nv_bfloat16*)(sm + 18432);
    __nv_bfloat16* Bs_hi = (__nv_bfloat16*)(sm + 36864);
    __nv_bfloat16* Bs_lo = (__nv_bfloat16*)(sm + 55296);
    float* Ds = (float*)sm;                 // 128 x 132 fp32, unions with staging
    float* ys = (float*)(sm + 73728);

    const int tid = threadIdx.x;
    const int wid = tid >> 5;
    const int m0 = blockIdx.x * 128;
    const int node0 = m0 >> 4;
    const int m_off = (wid & 1) * 64;       // 2 M-warps x 64 rows
    const int n_off = (wid >> 1) * 32;      // 4 N-warps x 32 cols

    // stage ys: 8 consecutive nodes x 512 = 4096 contiguous floats
    {
        const float4* src = (const float4*)(y + (size_t)node0 * HH);
        #pragma unroll
        for (int i = 0; i < 4; i++)
            ((float4*)ys)[tid + i * 256] = src[tid + i * 256];
    }

    float wsacc = 0.0f;

    for (int hc = 0; hc < 4; hc++) {        // 128 h-cols per chunk
        wmma::fragment<wmma::accumulator, 16, 16, 16, float> acc[4][2];
        #pragma unroll
        for (int mi = 0; mi < 4; mi++)
            #pragma unroll
            for (int ni = 0; ni < 2; ni++)
                wmma::fill_fragment(acc[mi][ni], 0.0f);

        for (int kc = 0; kc < KCH; kc++) {
            __syncthreads();   // prior mma / epilogue reads done before overwrite
            // A chunk: 128 rows x 64 cols (hi + lo)
            #pragma unroll
            for (int i = 0; i < 4; i++) {
                int g = tid + i * 256;              // 1024 granules of 8 bf16
                int row = g >> 3, c8 = (g & 7) * 8;
                size_t soff = (size_t)(m0 + row) * KD + kc * 64 + c8;
                *(int4*)(As_hi + row * 72 + c8) = *(const int4*)(Ahi + soff);
                *(int4*)(As_lo + row * 72 + c8) = *(const int4*)(Alo + soff);
            }
            // B chunk: 128 h-rows x 64 cols (hi + lo)
            #pragma unroll
            for (int i = 0; i < 4; i++) {
                int g = tid + i * 256;
                int row = g >> 3, c8 = (g & 7) * 8;
                size_t soff = (size_t)(hc * 128 + row) * KD + kc * 64 + c8;
                *(int4*)(Bs_hi + row * 72 + c8) = *(const int4*)(Whi + soff);
                *(int4*)(Bs_lo + row * 72 + c8) = *(const int4*)(Wlo + soff);
            }
            __syncthreads();

            #pragma unroll
            for (int ks = 0; ks < 4; ks++) {
                // B frags resident across the mi loop (4 frags)
                wmma::fragment<wmma::matrix_b, 16, 16, 16, __nv_bfloat16, wmma::col_major> bh[2], bl[2];
                #pragma unroll
                for (int ni = 0; ni < 2; ni++) {
                    wmma::load_matrix_sync(bh[ni], Bs_hi + (n_off + 16 * ni) * 72 + ks * 16, 72);
                    wmma::load_matrix_sync(bl[ni], Bs_lo + (n_off + 16 * ni) * 72 + ks * 16, 72);
                }
                // A frags loaded per-mi (transient) to bound register pressure
                #pragma unroll
                for (int mi = 0; mi < 4; mi++) {
                    wmma::fragment<wmma::matrix_a, 16, 16, 16, __nv_bfloat16, wmma::row_major> ah, al;
                    wmma::load_matrix_sync(ah, As_hi + (m_off + 16 * mi) * 72 + ks * 16, 72);
                    wmma::load_matrix_sync(al, As_lo + (m_off + 16 * mi) * 72 + ks * 16, 72);
                    #pragma unroll
                    for (int ni = 0; ni < 2; ni++) {
                        wmma::mma_sync(acc[mi][ni], ah, bh[ni], acc[mi][ni]);
                        wmma::mma_sync(acc[mi][ni], ah, bl[ni], acc[mi][ni]);
                        wmma::mma_sync(acc[mi][ni], al, bh[ni], acc[mi][ni]);
                    }
                }
            }
        }

        // epilogue: D tile (128x128) -> smem, tanh-dot with ys
        __syncthreads();
        #pragma unroll
        for (int mi = 0; mi < 4; mi++)
            #pragma unroll
            for (int ni = 0; ni < 2; ni++)
                wmma::store_matrix_sync(Ds + (m_off + 16 * mi) * 132 + n_off + 16 * ni,
                                        acc[mi][ni], 132, wmma::mem_row_major);
        __syncthreads();
        {
            int r = tid >> 1, ch = (tid & 1) * 64;
            const float* drow = Ds + r * 132 + ch;
            const float* yrow = ys + (r >> 4) * HH + hc * 128 + ch;
            float p = 0.0f;
            #pragma unroll
            for (int j = 0; j < 64; j++)
                p = fmaf(tanhf(drow[j]), yrow[j], p);
            wsacc += p;
        }
    }

    float other = __shfl_xor_sync(0xffffffffu, wsacc, 1);
    if ((tid & 1) == 0)
        ws[m0 + (tid >> 1)] = wsacc + other;
}

// ============================================================
// Generic fp32 tiled GEMM (the proven R5/R8 FFMA kernel)
// ============================================================
template<bool TRANSB, bool TANH, bool BIASRELU>
__global__ void __launch_bounds__(256)
gemm_kernel(const float* __restrict__ A, const float* __restrict__ B,
            const float* __restrict__ bias, float* __restrict__ C,
            int M, int Nc, int Kc, int ldc, int coff)
{
    __shared__ float As[16][128];
    __shared__ float Bs[16][128];
    const int tid = threadIdx.x;
    const int tx = tid & 15, ty = tid >> 4;
    const int m0 = blockIdx.y * 128;
    const int n0 = blockIdx.x * 128;

    const int ar = tid >> 2;
    const int ac = (tid & 3) * 4;

    float acc[8][8] = {};

    for (int k0 = 0; k0 < Kc; k0 += 16) {
        #pragma unroll
        for (int r = 0; r < 2; r++) {
            int row = ar + r * 64;
            float4 v = *(const float4*)(A + (size_t)(m0 + row) * Kc + k0 + ac);
            As[ac + 0][row] = v.x; As[ac + 1][row] = v.y;
            As[ac + 2][row] = v.z; As[ac + 3][row] = v.w;
        }
        if (TRANSB) {
            #pragma unroll
            for (int r = 0; r < 2; r++) {
                int row = ar + r * 64;
                float4 v = *(const float4*)(B + (size_t)(n0 + row) * Kc + k0 + ac);
                Bs[ac + 0][row] = v.x; Bs[ac + 1][row] = v.y;
                Bs[ac + 2][row] = v.z; Bs[ac + 3][row] = v.w;
            }
        } else {
            int kr = tid >> 5;
            int nc = (tid & 31) * 4;
            #pragma unroll
            for (int r = 0; r < 2; r++) {
                int krr = kr + r * 8;
                float4 v = *(const float4*)(B + (size_t)(k0 + krr) * Nc + n0 + nc);
                *(float4*)&Bs[krr][nc] = v;
            }
        }
        __syncthreads();
        #pragma unroll
        for (int kk = 0; kk < 16; kk++) {
            float af[8], bf[8];
            *(float4*)&af[0] = *(const float4*)&As[kk][ty * 8];
            *(float4*)&af[4] = *(const float4*)&As[kk][ty * 8 + 4];
            *(float4*)&bf[0] = *(const float4*)&Bs[kk][tx * 8];
            *(float4*)&bf[4] = *(const float4*)&Bs[kk][tx * 8 + 4];
            #pragma unroll
            for (int i = 0; i < 8; i++)
                #pragma unroll
                for (int j = 0; j < 8; j++)
                    acc[i][j] = fmaf(af[i], bf[j], acc[i][j]);
        }
        __syncthreads();
    }

    #pragma unroll
    for (int i = 0; i < 8; i++) {
        int row = m0 + ty * 8 + i;
        #pragma unroll
        for (int jv = 0; jv < 2; jv++) {
            float4 v;
            float* vv = (float*)&v;
            #pragma unroll
            for (int j = 0; j < 4; j++) {
                int col = tx * 8 + jv * 4 + j;
                float val = acc[i][jv * 4 + j];
                if (TANH) val = tanhf(val);
                if (BIASRELU) { val += bias[n0 + col]; val = fmaxf(val, 0.0f); }
                vv[j] = val;
            }
            *(float4*)(C + (size_t)row * ldc + coff + n0 + tx * 8 + jv * 4) = v;
        }
    }
}

// ============================================================
// Softmax (scaled / masked) + weighted aggregation (unchanged)
// ============================================================
__global__ void __launch_bounds__(128)
softmax_agg(const float* __restrict__ wsn, const float* __restrict__ wse,
            const int* __restrict__ mask, const float* __restrict__ neibs,
            const float* __restrict__ edges,
            float* __restrict__ aggn, float* __restrict__ agge)
{
    const int n = blockIdx.x;
    const int tid = threadIdx.x;
    __shared__ float s1[16], s2[16];
    if (tid < 16) {
        s1[tid] = wsn[n * 16 + tid] * 0.04419417382415922f;  // 1/sqrt(512)
        s2[tid] = wse[n * 16 + tid] - 9999999.0f * (float)mask[n * 16 + tid];
    }
    __syncthreads();

    float w1[16], w2[16];
    float m1 = -1e30f, m2 = -1e30f;
    #pragma unroll
    for (int k = 0; k < 16; k++) {
        m1 = fmaxf(m1, s1[k]);
        m2 = fmaxf(m2, s2[k]);
    }
    float t1 = 0.0f, t2 = 0.0f;
    #pragma unroll
    for (int k = 0; k < 16; k++) {
        w1[k] = expf(s1[k] - m1); t1 += w1[k];
        w2[k] = expf(s2[k] - m2); t2 += w2[k];
    }
    const float r1 = 1.0f / t1, r2 = 1.0f / t2;

    #pragma unroll
    for (int p = 0; p < 2; p++) {
        int d = tid + p * 128;
        float acc = 0.0f;
        #pragma unroll
        for (int k = 0; k < 16; k++)
            acc = fmaf(w1[k], neibs[((size_t)n * 16 + k) * DD + d], acc);
        aggn[(size_t)n * DD + d] = acc * r1;
    }
    {
        int d = tid;
        float acc = 0.0f;
        #pragma unroll
        for (int k = 0; k < 16; k++)
            acc = fmaf(w2[k], edges[((size_t)n * 16 + k) * EE + d], acc);
        agge[(size_t)n * EE + d] = acc * r2;
    }
}

// ============================================================
extern "C" void kernel_launch(void* const* d_in, const int* in_sizes, int n_in,
                              void* d_out, int out_size)
{
    const float* x     = (const float*)d_in[0];
    const float* neibs = (const float*)d_in[1];
    const float* edge  = (const float*)d_in[2];
    const int*   mask  = (const int*)  d_in[3];
    const float* W1x   = (const float*)d_in[4];
    const float* W2x   = (const float*)d_in[5];
    const float* W1n   = (const float*)d_in[6];
    const float* W2n   = (const float*)d_in[7];
    const float* W1e   = (const float*)d_in[8];
    const float* W2e   = (const float*)d_in[9];
    const float* Wfx   = (const float*)d_in[10];
    const float* bfx   = (const float*)d_in[11];
    const float* Wfn   = (const float*)d_in[12];
    const float* bfn   = (const float*)d_in[13];
    const float* Wfe   = (const float*)d_in[14];
    const float* bfe   = (const float*)d_in[15];
    float* out = (float*)d_out;

    float *h1, *xatt, *yn, *ye, *wsn, *wse, *aggn, *agge;
    cudaGetSymbolAddress((void**)&h1,   g_h1);
    cudaGetSymbolAddress((void**)&xatt, g_xatt);
    cudaGetSymbolAddress((void**)&yn,   g_yn);
    cudaGetSymbolAddress((void**)&ye,   g_ye);
    cudaGetSymbolAddress((void**)&wsn,  g_wsn);
    cudaGetSymbolAddress((void**)&wse,  g_wse);
    cudaGetSymbolAddress((void**)&aggn, g_aggn);
    cudaGetSymbolAddress((void**)&agge, g_agge);

    __nv_bfloat16 *nhi, *nlo, *ehi, *elo, *w1nhi, *w1nlo, *w1ehi, *w1elo;
    cudaGetSymbolAddress((void**)&nhi,   g_nhi);
    cudaGetSymbolAddress((void**)&nlo,   g_nlo);
    cudaGetSymbolAddress((void**)&ehi,   g_ehi);
    cudaGetSymbolAddress((void**)&elo,   g_elo);
    cudaGetSymbolAddress((void**)&w1nhi, g_w1nhi);
    cudaGetSymbolAddress((void**)&w1nlo, g_w1nlo);
    cudaGetSymbolAddress((void**)&w1ehi, g_w1ehi);
    cudaGetSymbolAddress((void**)&w1elo, g_w1elo);

    cudaFuncSetAttribute(ws_mma<DD>, cudaFuncAttributeMaxDynamicSharedMemorySize, WS3_SMEM);
    cudaFuncSetAttribute(ws_mma<EE>, cudaFuncAttributeMaxDynamicSharedMemorySize, WS3_SMEM);

    dim3 blk(256);

    // bf16 hi/lo splits (ws inputs only)
    {
        int n4;
        n4 = NN * KNB * DD / 4; split_kernel<<<(n4 + 255) / 256, 256>>>(neibs, nhi, nlo, n4);
        n4 = NN * KNB * EE / 4; split_kernel<<<(n4 + 255) / 256, 256>>>(edge,  ehi, elo, n4);
        n4 = HH * DD / 4;       split_kernel<<<(n4 + 255) / 256, 256>>>(W1n, w1nhi, w1nlo, n4);
        n4 = HH * EE / 4;       split_kernel<<<(n4 + 255) / 256, 256>>>(W1e, w1ehi, w1elo, n4);
    }

    // x_att pipeline (8192 rows) — FFMA (R9 showed WMMA is slower here)
    gemm_kernel<true,  true,  false><<<dim3(HH/128, NN/128), blk>>>(x,    W1x, nullptr, h1,   NN, HH, DD, HH, 0);
    gemm_kernel<true,  false, false><<<dim3(HH/128, NN/128), blk>>>(h1,   W2x, nullptr, xatt, NN, HH, HH, HH, 0);
    gemm_kernel<false, false, false><<<dim3(HH/128, NN/128), blk>>>(xatt, W2n, nullptr, yn,   NN, HH, HH, HH, 0);
    gemm_kernel<false, false, false><<<dim3(HH/128, NN/128), blk>>>(xatt, W2e, nullptr, ye,   NN, HH, HH, HH, 0);

    // attention logits on tensor cores (bf16 hi/lo 3-term via mma.sync)
    ws_mma<DD><<<(NN * KNB) / 128, blk, WS3_SMEM>>>(nhi, nlo, w1nhi, w1nlo, yn, wsn);
    ws_mma<EE><<<(NN * KNB) / 128, blk, WS3_SMEM>>>(ehi, elo, w1ehi, w1elo, ye, wse);

    // softmax + aggregation
    softmax_agg<<<NN, 128>>>(wsn, wse, mask, neibs, edge, aggn, agge);

    // final linears + bias + relu, strided into [8192, 768] output
    gemm_kernel<true, false, true><<<dim3(OO/128, NN/128), blk>>>(x,    Wfx, bfx, out, NN, OO, DD, 3*OO, 0);
    gemm_kernel<true, false, true><<<dim3(OO/128, NN/128), blk>>>(aggn, Wfn, bfn, out, NN, OO, DD, 3*OO, OO);
    gemm_kernel<true, false, true><<<dim3(OO/128, NN/128), blk>>>(agge, Wfe, bfe, out, NN, OO, EE, 3*OO, 2*OO);
}

// round 11
// speedup vs baseline: 1.6783x; 1.2666x over previous
#include <cuda_runtime.h>
#include <cuda_bf16.h>
#include <mma.h>
#include <math.h>
#include <stdint.h>

using namespace nvcuda;

#define NN 8192
#define KNB 16
#define DD 256
#define EE 128
#define HH 512
#define OO 256

// ---- scratch (no allocations allowed; __device__ globals) ----
__device__ float g_yn[NN * HH];
__device__ float g_ye[NN * HH];
__device__ float g_wsn[NN * KNB];
__device__ float g_wse[NN * KNB];
__device__ float g_aggn[NN * DD];
__device__ float g_agge[NN * EE];
// bf16 hi/lo splits: ws inputs
__device__ __nv_bfloat16 g_nhi[NN * KNB * DD];
__device__ __nv_bfloat16 g_nlo[NN * KNB * DD];
__device__ __nv_bfloat16 g_ehi[NN * KNB * EE];
__device__ __nv_bfloat16 g_elo[NN * KNB * EE];
__device__ __nv_bfloat16 g_w1nhi[HH * DD];
__device__ __nv_bfloat16 g_w1nlo[HH * DD];
__device__ __nv_bfloat16 g_w1ehi[HH * EE];
__device__ __nv_bfloat16 g_w1elo[HH * EE];
// chain inputs/activations (hi/lo)
__device__ __nv_bfloat16 g_xhi[NN * DD];
__device__ __nv_bfloat16 g_xlo[NN * DD];
__device__ __nv_bfloat16 g_h1hi[NN * HH];
__device__ __nv_bfloat16 g_h1lo[NN * HH];
__device__ __nv_bfloat16 g_xahi[NN * HH];
__device__ __nv_bfloat16 g_xalo[NN * HH];
__device__ __nv_bfloat16 g_anhi[NN * DD];
__device__ __nv_bfloat16 g_anlo[NN * DD];
__device__ __nv_bfloat16 g_aehi[NN * EE];
__device__ __nv_bfloat16 g_aelo[NN * EE];
// weight splits
__device__ __nv_bfloat16 g_w1xhi[HH * DD];
__device__ __nv_bfloat16 g_w1xlo[HH * DD];
__device__ __nv_bfloat16 g_w2xhi[HH * HH];
__device__ __nv_bfloat16 g_w2xlo[HH * HH];
__device__ __nv_bfloat16 g_w2nhi[HH * HH];
__device__ __nv_bfloat16 g_w2nlo[HH * HH];
__device__ __nv_bfloat16 g_w2ehi[HH * HH];
__device__ __nv_bfloat16 g_w2elo[HH * HH];
__device__ __nv_bfloat16 g_wfxhi[OO * DD];
__device__ __nv_bfloat16 g_wfxlo[OO * DD];
__device__ __nv_bfloat16 g_wfnhi[OO * DD];
__device__ __nv_bfloat16 g_wfnlo[OO * DD];
__device__ __nv_bfloat16 g_wfehi[OO * EE];
__device__ __nv_bfloat16 g_wfelo[OO * EE];

// ============================================================
// fp32 -> bf16 hi/lo split (elementwise, float4-vectorized)
// ============================================================
__global__ void __launch_bounds__(256)
split_kernel(const float* __restrict__ src, __nv_bfloat16* __restrict__ hi,
             __nv_bfloat16* __restrict__ lo, int n4)
{
    int i = blockIdx.x * blockDim.x + threadIdx.x;
    if (i >= n4) return;
    float4 v = ((const float4*)src)[i];
    __nv_bfloat162 h01 = __floats2bfloat162_rn(v.x, v.y);
    __nv_bfloat162 h23 = __floats2bfloat162_rn(v.z, v.w);
    float rx = v.x - __bfloat162float(h01.x);
    float ry = v.y - __bfloat162float(h01.y);
    float rz = v.z - __bfloat162float(h23.x);
    float rw = v.w - __bfloat162float(h23.y);
    __nv_bfloat162 l01 = __floats2bfloat162_rn(rx, ry);
    __nv_bfloat162 l23 = __floats2bfloat162_rn(rz, rw);
    uint2 ho, loo;
    ho.x  = *(uint32_t*)&h01; ho.y  = *(uint32_t*)&h23;
    loo.x = *(uint32_t*)&l01; loo.y = *(uint32_t*)&l23;
    ((uint2*)hi)[i] = ho;
    ((uint2*)lo)[i] = loo;
}

// ============================================================
// B-fragment handling: BT=true -> B is [N,K] K-major; staged 128(n) x 72
//                      BT=false -> B is [K,N] N-major; staged 64(k) x 136
// ============================================================
template<bool BT> struct BFrag;
template<> struct BFrag<true> {
    using T = wmma::fragment<wmma::matrix_b, 16, 16, 16, __nv_bfloat16, wmma::col_major>;
    static __device__ __forceinline__ void load(T& f, const __nv_bfloat16* base,
                                                int n_idx, int ks) {
        wmma::load_matrix_sync(f, base + n_idx * 72 + ks * 16, 72);
    }
};
template<> struct BFrag<false> {
    using T = wmma::fragment<wmma::matrix_b, 16, 16, 16, __nv_bfloat16, wmma::row_major>;
    static __device__ __forceinline__ void load(T& f, const __nv_bfloat16* base,
                                                int n_idx, int ks) {
        wmma::load_matrix_sync(f, base + (ks * 16) * 136 + n_idx, 136);
    }
};

// ============================================================
// Generic WMMA GEMM with the PROVEN R10 tile structure:
//   tile 128(M) x 128(N), 8 warps = 2(M) x 4(N), warp 64x32 (4x2 frags),
//   K staged 64-wide, bf16 hi/lo 3-term (~fp32 accuracy).
//   C[M,Nc] = act( A[M,Kc] @ op(B) )
// SPLITOUT: write hi/lo bf16 (chained GEMMs). Else fp32 (+bias/relu).
// grid = (Nc/128, M/128). Kc % 64 == 0.
// ============================================================
// dyn smem:
//   [0]      As_hi 128x72 bf16 (18432)  } union with Ds 128x132 fp32 (67584)
//   [18432]  As_lo (18432)              }
//   [36864]  Bs_hi (18432: 128x72 BT / 64x136 notBT=17408)
//   [55296]  Bs_lo (18432)
#define WG2_SMEM 73728

template<bool BT, bool TANH_, bool BIASRELU_, bool SPLITOUT>
__global__ void __launch_bounds__(256, 2)
wgemm2(const __nv_bfloat16* __restrict__ Ahi, const __nv_bfloat16* __restrict__ Alo,
       const __nv_bfloat16* __restrict__ Bhi, const __nv_bfloat16* __restrict__ Blo,
       const float* __restrict__ bias,
       float* __restrict__ Cf, __nv_bfloat16* __restrict__ Chi, __nv_bfloat16* __restrict__ Clo,
       int Nc, int Kc, int ldc, int coff)
{
    extern __shared__ char sm[];
    __nv_bfloat16* As_hi = (__nv_bfloat16*)(sm);
    __nv_bfloat16* As_lo = (__nv_bfloat16*)(sm + 18432);
    __nv_bfloat16* Bs_hi = (__nv_bfloat16*)(sm + 36864);
    __nv_bfloat16* Bs_lo = (__nv_bfloat16*)(sm + 55296);
    float* Ds = (float*)sm;

    const int tid = threadIdx.x;
    const int wid = tid >> 5;
    const int m0 = blockIdx.y * 128;
    const int n0 = blockIdx.x * 128;
    const int m_off = (wid & 1) * 64;
    const int n_off = (wid >> 1) * 32;

    wmma::fragment<wmma::accumulator, 16, 16, 16, float> acc[4][2];
    #pragma unroll
    for (int mi = 0; mi < 4; mi++)
        #pragma unroll
        for (int ni = 0; ni < 2; ni++)
            wmma::fill_fragment(acc[mi][ni], 0.0f);

    const int KCH = Kc >> 6;
    for (int kc = 0; kc < KCH; kc++) {
        __syncthreads();
        // stage A: 128 rows x 64 k (hi + lo)
        #pragma unroll
        for (int i = 0; i < 4; i++) {
            int g = tid + i * 256;
            int row = g >> 3, c8 = (g & 7) * 8;
            size_t soff = (size_t)(m0 + row) * Kc + kc * 64 + c8;
            *(int4*)(As_hi + row * 72 + c8) = *(const int4*)(Ahi + soff);
            *(int4*)(As_lo + row * 72 + c8) = *(const int4*)(Alo + soff);
        }
        // stage B
        if (BT) {
            #pragma unroll
            for (int i = 0; i < 4; i++) {
                int g = tid + i * 256;
                int row = g >> 3, c8 = (g & 7) * 8;       // row = n (0..127)
                size_t soff = (size_t)(n0 + row) * Kc + kc * 64 + c8;
                *(int4*)(Bs_hi + row * 72 + c8) = *(const int4*)(Bhi + soff);
                *(int4*)(Bs_lo + row * 72 + c8) = *(const int4*)(Blo + soff);
            }
        } else {
            #pragma unroll
            for (int i = 0; i < 4; i++) {
                int g = tid + i * 256;
                int row = g >> 4, c8 = (g & 15) * 8;      // row = k (0..63)
                size_t soff = (size_t)(kc * 64 + row) * Nc + n0 + c8;
                *(int4*)(Bs_hi + row * 136 + c8) = *(const int4*)(Bhi + soff);
                *(int4*)(Bs_lo + row * 136 + c8) = *(const int4*)(Blo + soff);
            }
        }
        __syncthreads();

        #pragma unroll
        for (int ks = 0; ks < 4; ks++) {
            typename BFrag<BT>::T bh[2], bl[2];
            #pragma unroll
            for (int ni = 0; ni < 2; ni++) {
                BFrag<BT>::load(bh[ni], Bs_hi, n_off + 16 * ni, ks);
                BFrag<BT>::load(bl[ni], Bs_lo, n_off + 16 * ni, ks);
            }
            #pragma unroll
            for (int mi = 0; mi < 4; mi++) {
                wmma::fragment<wmma::matrix_a, 16, 16, 16, __nv_bfloat16, wmma::row_major> ah, al;
                wmma::load_matrix_sync(ah, As_hi + (m_off + 16 * mi) * 72 + ks * 16, 72);
                wmma::load_matrix_sync(al, As_lo + (m_off + 16 * mi) * 72 + ks * 16, 72);
                #pragma unroll
                for (int ni = 0; ni < 2; ni++) {
                    wmma::mma_sync(acc[mi][ni], ah, bh[ni], acc[mi][ni]);
                    wmma::mma_sync(acc[mi][ni], ah, bl[ni], acc[mi][ni]);
                    wmma::mma_sync(acc[mi][ni], al, bh[ni], acc[mi][ni]);
                }
            }
        }
    }

    // epilogue via smem Ds (128 x 132)
    __syncthreads();
    #pragma unroll
    for (int mi = 0; mi < 4; mi++)
        #pragma unroll
        for (int ni = 0; ni < 2; ni++)
            wmma::store_matrix_sync(Ds + (m_off + 16 * mi) * 132 + n_off + 16 * ni,
                                    acc[mi][ni], 132, wmma::mem_row_major);
    __syncthreads();

    const int r = tid >> 1, ch = (tid & 1) * 64;
    const float* drow = Ds + r * 132 + ch;
    if (SPLITOUT) {
        #pragma unroll
        for (int j4 = 0; j4 < 8; j4++) {
            float v[8];
            #pragma unroll
            for (int jj = 0; jj < 8; jj++) {
                float t = drow[j4 * 8 + jj];
                v[jj] = TANH_ ? tanhf(t) : t;
            }
            uint4 ho, lo;
            uint32_t* hp = (uint32_t*)&ho;
            uint32_t* lp = (uint32_t*)&lo;
            #pragma unroll
            for (int p = 0; p < 4; p++) {
                __nv_bfloat162 h = __floats2bfloat162_rn(v[2 * p], v[2 * p + 1]);
                float r0 = v[2 * p]     - __bfloat162float(h.x);
                float r1 = v[2 * p + 1] - __bfloat162float(h.y);
                __nv_bfloat162 l = __floats2bfloat162_rn(r0, r1);
                hp[p] = *(uint32_t*)&h;
                lp[p] = *(uint32_t*)&l;
            }
            size_t o = (size_t)(m0 + r) * ldc + coff + n0 + ch + j4 * 8;
            *(uint4*)(Chi + o) = ho;
            *(uint4*)(Clo + o) = lo;
        }
    } else {
        #pragma unroll
        for (int jv = 0; jv < 16; jv++) {
            float4 vv;
            float* vp = (float*)&vv;
            #pragma unroll
            for (int j = 0; j < 4; j++) {
                int col = n0 + ch + jv * 4 + j;
                float val = drow[jv * 4 + j];
                if (TANH_) val = tanhf(val);
                if (BIASRELU_) { val += bias[col]; val = fmaxf(val, 0.0f); }
                vp[j] = val;
            }
            *(float4*)(Cf + (size_t)(m0 + r) * ldc + coff + n0 + ch + jv * 4) = vv;
        }
    }
}

// ============================================================
// Tensor-core fused logit kernel (UNCHANGED from passing R10)
// ============================================================
#define WS3_SMEM 90112

template<int KD>
__global__ void __launch_bounds__(256, 2)
ws_mma(const __nv_bfloat16* __restrict__ Ahi, const __nv_bfloat16* __restrict__ Alo,
       const __nv_bfloat16* __restrict__ Whi, const __nv_bfloat16* __restrict__ Wlo,
       const float* __restrict__ y, float* __restrict__ ws)
{
    extern __shared__ char sm[];
    constexpr int KCH = KD / 64;

    __nv_bfloat16* As_hi = (__nv_bfloat16*)(sm);
    __nv_bfloat16* As_lo = (__nv_bfloat16*)(sm + 18432);
    __nv_bfloat16* Bs_hi = (__nv_bfloat16*)(sm + 36864);
    __nv_bfloat16* Bs_lo = (__nv_bfloat16*)(sm + 55296);
    float* Ds = (float*)sm;
    float* ys = (float*)(sm + 73728);

    const int tid = threadIdx.x;
    const int wid = tid >> 5;
    const int m0 = blockIdx.x * 128;
    const int node0 = m0 >> 4;
    const int m_off = (wid & 1) * 64;
    const int n_off = (wid >> 1) * 32;

    {
        const float4* src = (const float4*)(y + (size_t)node0 * HH);
        #pragma unroll
        for (int i = 0; i < 4; i++)
            ((float4*)ys)[tid + i * 256] = src[tid + i * 256];
    }

    float wsacc = 0.0f;

    for (int hc = 0; hc < 4; hc++) {
        wmma::fragment<wmma::accumulator, 16, 16, 16, float> acc[4][2];
        #pragma unroll
        for (int mi = 0; mi < 4; mi++)
            #pragma unroll
            for (int ni = 0; ni < 2; ni++)
                wmma::fill_fragment(acc[mi][ni], 0.0f);

        for (int kc = 0; kc < KCH; kc++) {
            __syncthreads();
            #pragma unroll
            for (int i = 0; i < 4; i++) {
                int g = tid + i * 256;
                int row = g >> 3, c8 = (g & 7) * 8;
                size_t soff = (size_t)(m0 + row) * KD + kc * 64 + c8;
                *(int4*)(As_hi + row * 72 + c8) = *(const int4*)(Ahi + soff);
                *(int4*)(As_lo + row * 72 + c8) = *(const int4*)(Alo + soff);
            }
            #pragma unroll
            for (int i = 0; i < 4; i++) {
                int g = tid + i * 256;
                int row = g >> 3, c8 = (g & 7) * 8;
                size_t soff = (size_t)(hc * 128 + row) * KD + kc * 64 + c8;
                *(int4*)(Bs_hi + row * 72 + c8) = *(const int4*)(Whi + soff);
                *(int4*)(Bs_lo + row * 72 + c8) = *(const int4*)(Wlo + soff);
            }
            __syncthreads();

            #pragma unroll
            for (int ks = 0; ks < 4; ks++) {
                wmma::fragment<wmma::matrix_b, 16, 16, 16, __nv_bfloat16, wmma::col_major> bh[2], bl[2];
                #pragma unroll
                for (int ni = 0; ni < 2; ni++) {
                    wmma::load_matrix_sync(bh[ni], Bs_hi + (n_off + 16 * ni) * 72 + ks * 16, 72);
                    wmma::load_matrix_sync(bl[ni], Bs_lo + (n_off + 16 * ni) * 72 + ks * 16, 72);
                }
                #pragma unroll
                for (int mi = 0; mi < 4; mi++) {
                    wmma::fragment<wmma::matrix_a, 16, 16, 16, __nv_bfloat16, wmma::row_major> ah, al;
                    wmma::load_matrix_sync(ah, As_hi + (m_off + 16 * mi) * 72 + ks * 16, 72);
                    wmma::load_matrix_sync(al, As_lo + (m_off + 16 * mi) * 72 + ks * 16, 72);
                    #pragma unroll
                    for (int ni = 0; ni < 2; ni++) {
                        wmma::mma_sync(acc[mi][ni], ah, bh[ni], acc[mi][ni]);
                        wmma::mma_sync(acc[mi][ni], ah, bl[ni], acc[mi][ni]);
                        wmma::mma_sync(acc[mi][ni], al, bh[ni], acc[mi][ni]);
                    }
                }
            }
        }

        __syncthreads();
        #pragma unroll
        for (int mi = 0; mi < 4; mi++)
            #pragma unroll
            for (int ni = 0; ni < 2; ni++)
                wmma::store_matrix_sync(Ds + (m_off + 16 * mi) * 132 + n_off + 16 * ni,
                                        acc[mi][ni], 132, wmma::mem_row_major);
        __syncthreads();
        {
            int r = tid >> 1, ch = (tid & 1) * 64;
            const float* drow = Ds + r * 132 + ch;
            const float* yrow = ys + (r >> 4) * HH + hc * 128 + ch;
            float p = 0.0f;
            #pragma unroll
            for (int j = 0; j < 64; j++)
                p = fmaf(tanhf(drow[j]), yrow[j], p);
            wsacc += p;
        }
    }

    float other = __shfl_xor_sync(0xffffffffu, wsacc, 1);
    if ((tid & 1) == 0)
        ws[m0 + (tid >> 1)] = wsacc + other;
}

// ============================================================
// Softmax (scaled / masked) + weighted aggregation (unchanged)
// ============================================================
__global__ void __launch_bounds__(128)
softmax_agg(const float* __restrict__ wsn, const float* __restrict__ wse,
            const int* __restrict__ mask, const float* __restrict__ neibs,
            const float* __restrict__ edges,
            float* __restrict__ aggn, float* __restrict__ agge)
{
    const int n = blockIdx.x;
    const int tid = threadIdx.x;
    __shared__ float s1[16], s2[16];
    if (tid < 16) {
        s1[tid] = wsn[n * 16 + tid] * 0.04419417382415922f;  // 1/sqrt(512)
        s2[tid] = wse[n * 16 + tid] - 9999999.0f * (float)mask[n * 16 + tid];
    }
    __syncthreads();

    float w1[16], w2[16];
    float m1 = -1e30f, m2 = -1e30f;
    #pragma unroll
    for (int k = 0; k < 16; k++) {
        m1 = fmaxf(m1, s1[k]);
        m2 = fmaxf(m2, s2[k]);
    }
    float t1 = 0.0f, t2 = 0.0f;
    #pragma unroll
    for (int k = 0; k < 16; k++) {
        w1[k] = expf(s1[k] - m1); t1 += w1[k];
        w2[k] = expf(s2[k] - m2); t2 += w2[k];
    }
    const float r1 = 1.0f / t1, r2 = 1.0f / t2;

    #pragma unroll
    for (int p = 0; p < 2; p++) {
        int d = tid + p * 128;
        float acc = 0.0f;
        #pragma unroll
        for (int k = 0; k < 16; k++)
            acc = fmaf(w1[k], neibs[((size_t)n * 16 + k) * DD + d], acc);
        aggn[(size_t)n * DD + d] = acc * r1;
    }
    {
        int d = tid;
        float acc = 0.0f;
        #pragma unroll
        for (int k = 0; k < 16; k++)
            acc = fmaf(w2[k], edges[((size_t)n * 16 + k) * EE + d], acc);
        agge[(size_t)n * EE + d] = acc * r2;
    }
}

// ============================================================
extern "C" void kernel_launch(void* const* d_in, const int* in_sizes, int n_in,
                              void* d_out, int out_size)
{
    const float* x     = (const float*)d_in[0];
    const float* neibs = (const float*)d_in[1];
    const float* edge  = (const float*)d_in[2];
    const int*   mask  = (const int*)  d_in[3];
    const float* W1x   = (const float*)d_in[4];
    const float* W2x   = (const float*)d_in[5];
    const float* W1n   = (const float*)d_in[6];
    const float* W2n   = (const float*)d_in[7];
    const float* W1e   = (const float*)d_in[8];
    const float* W2e   = (const float*)d_in[9];
    const float* Wfx   = (const float*)d_in[10];
    const float* bfx   = (const float*)d_in[11];
    const float* Wfn   = (const float*)d_in[12];
    const float* bfn   = (const float*)d_in[13];
    const float* Wfe   = (const float*)d_in[14];
    const float* bfe   = (const float*)d_in[15];
    float* out = (float*)d_out;

    float *yn, *ye, *wsn, *wse, *aggn, *agge;
    cudaGetSymbolAddress((void**)&yn,   g_yn);
    cudaGetSymbolAddress((void**)&ye,   g_ye);
    cudaGetSymbolAddress((void**)&wsn,  g_wsn);
    cudaGetSymbolAddress((void**)&wse,  g_wse);
    cudaGetSymbolAddress((void**)&aggn, g_aggn);
    cudaGetSymbolAddress((void**)&agge, g_agge);

    __nv_bfloat16 *nhi, *nlo, *ehi, *elo, *w1nhi, *w1nlo, *w1ehi, *w1elo;
    __nv_bfloat16 *xhi, *xlo, *h1hi, *h1lo, *xahi, *xalo, *anhi, *anlo, *aehi, *aelo;
    __nv_bfloat16 *w1xhi, *w1xlo, *w2xhi, *w2xlo, *w2nhi, *w2nlo, *w2ehi, *w2elo;
    __nv_bfloat16 *wfxhi, *wfxlo, *wfnhi, *wfnlo, *wfehi, *wfelo;
    cudaGetSymbolAddress((void**)&nhi,   g_nhi);
    cudaGetSymbolAddress((void**)&nlo,   g_nlo);
    cudaGetSymbolAddress((void**)&ehi,   g_ehi);
    cudaGetSymbolAddress((void**)&elo,   g_elo);
    cudaGetSymbolAddress((void**)&w1nhi, g_w1nhi);
    cudaGetSymbolAddress((void**)&w1nlo, g_w1nlo);
    cudaGetSymbolAddress((void**)&w1ehi, g_w1ehi);
    cudaGetSymbolAddress((void**)&w1elo, g_w1elo);
    cudaGetSymbolAddress((void**)&xhi,   g_xhi);
    cudaGetSymbolAddress((void**)&xlo,   g_xlo);
    cudaGetSymbolAddress((void**)&h1hi,  g_h1hi);
    cudaGetSymbolAddress((void**)&h1lo,  g_h1lo);
    cudaGetSymbolAddress((void**)&xahi,  g_xahi);
    cudaGetSymbolAddress((void**)&xalo,  g_xalo);
    cudaGetSymbolAddress((void**)&anhi,  g_anhi);
    cudaGetSymbolAddress((void**)&anlo,  g_anlo);
    cudaGetSymbolAddress((void**)&aehi,  g_aehi);
    cudaGetSymbolAddress((void**)&aelo,  g_aelo);
    cudaGetSymbolAddress((void**)&w1xhi, g_w1xhi);
    cudaGetSymbolAddress((void**)&w1xlo, g_w1xlo);
    cudaGetSymbolAddress((void**)&w2xhi, g_w2xhi);
    cudaGetSymbolAddress((void**)&w2xlo, g_w2xlo);
    cudaGetSymbolAddress((void**)&w2nhi, g_w2nhi);
    cudaGetSymbolAddress((void**)&w2nlo, g_w2nlo);
    cudaGetSymbolAddress((void**)&w2ehi, g_w2ehi);
    cudaGetSymbolAddress((void**)&w2elo, g_w2elo);
    cudaGetSymbolAddress((void**)&wfxhi, g_wfxhi);
    cudaGetSymbolAddress((void**)&wfxlo, g_wfxlo);
    cudaGetSymbolAddress((void**)&wfnhi, g_wfnhi);
    cudaGetSymbolAddress((void**)&wfnlo, g_wfnlo);
    cudaGetSymbolAddress((void**)&wfehi, g_wfehi);
    cudaGetSymbolAddress((void**)&wfelo, g_wfelo);

    cudaFuncSetAttribute(ws_mma<DD>, cudaFuncAttributeMaxDynamicSharedMemorySize, WS3_SMEM);
    cudaFuncSetAttribute(ws_mma<EE>, cudaFuncAttributeMaxDynamicSharedMemorySize, WS3_SMEM);
    cudaFuncSetAttribute(wgemm2<true,  true,  false, true >, cudaFuncAttributeMaxDynamicSharedMemorySize, WG2_SMEM);
    cudaFuncSetAttribute(wgemm2<true,  false, false, true >, cudaFuncAttributeMaxDynamicSharedMemorySize, WG2_SMEM);
    cudaFuncSetAttribute(wgemm2<false, false, false, false>, cudaFuncAttributeMaxDynamicSharedMemorySize, WG2_SMEM);
    cudaFuncSetAttribute(wgemm2<true,  false, true,  false>, cudaFuncAttributeMaxDynamicSharedMemorySize, WG2_SMEM);

    dim3 blk(256);

    // ---- splits ----
    split_kernel<<<(NN*DD/4 + 255)/256, blk>>>(x,   xhi,   xlo,   NN*DD/4);
    split_kernel<<<(HH*DD/4 + 255)/256, blk>>>(W1x, w1xhi, w1xlo, HH*DD/4);
    split_kernel<<<(HH*HH/4 + 255)/256, blk>>>(W2x, w2xhi, w2xlo, HH*HH/4);
    split_kernel<<<(HH*HH/4 + 255)/256, blk>>>(W2n, w2nhi, w2nlo, HH*HH/4);
    split_kernel<<<(HH*HH/4 + 255)/256, blk>>>(W2e, w2ehi, w2elo, HH*HH/4);
    split_kernel<<<(NN*KNB*DD/4 + 255)/256, blk>>>(neibs, nhi, nlo, NN*KNB*DD/4);
    split_kernel<<<(NN*KNB*EE/4 + 255)/256, blk>>>(edge,  ehi, elo, NN*KNB*EE/4);
    split_kernel<<<(HH*DD/4 + 255)/256, blk>>>(W1n, w1nhi, w1nlo, HH*DD/4);
    split_kernel<<<(HH*EE/4 + 255)/256, blk>>>(W1e, w1ehi, w1elo, HH*EE/4);
    split_kernel<<<(OO*DD/4 + 255)/256, blk>>>(Wfx, wfxhi, wfxlo, OO*DD/4);
    split_kernel<<<(OO*DD/4 + 255)/256, blk>>>(Wfn, wfnhi, wfnlo, OO*DD/4);
    split_kernel<<<(OO*EE/4 + 255)/256, blk>>>(Wfe, wfehi, wfelo, OO*EE/4);

    // ---- x_att chain on tensor cores (128x128 tiles) ----
    wgemm2<true, true, false, true><<<dim3(HH/128, NN/128), blk, WG2_SMEM>>>(
        xhi, xlo, w1xhi, w1xlo, nullptr, nullptr, h1hi, h1lo, HH, DD, HH, 0);
    wgemm2<true, false, false, true><<<dim3(HH/128, NN/128), blk, WG2_SMEM>>>(
        h1hi, h1lo, w2xhi, w2xlo, nullptr, nullptr, xahi, xalo, HH, HH, HH, 0);
    wgemm2<false, false, false, false><<<dim3(HH/128, NN/128), blk, WG2_SMEM>>>(
        xahi, xalo, w2nhi, w2nlo, nullptr, yn, nullptr, nullptr, HH, HH, HH, 0);
    wgemm2<false, false, false, false><<<dim3(HH/128, NN/128), blk, WG2_SMEM>>>(
        xahi, xalo, w2ehi, w2elo, nullptr, ye, nullptr, nullptr, HH, HH, HH, 0);

    // ---- attention logits (tensor cores, unchanged R10) ----
    ws_mma<DD><<<(NN * KNB) / 128, blk, WS3_SMEM>>>(nhi, nlo, w1nhi, w1nlo, yn, wsn);
    ws_mma<EE><<<(NN * KNB) / 128, blk, WS3_SMEM>>>(ehi, elo, w1ehi, w1elo, ye, wse);

    // ---- softmax + aggregation ----
    softmax_agg<<<NN, 128>>>(wsn, wse, mask, neibs, edge, aggn, agge);

    // ---- output GEMMs on tensor cores ----
    split_kernel<<<(NN*DD/4 + 255)/256, blk>>>(aggn, anhi, anlo, NN*DD/4);
    split_kernel<<<(NN*EE/4 + 255)/256, blk>>>(agge, aehi, aelo, NN*EE/4);

    wgemm2<true, false, true, false><<<dim3(OO/128, NN/128), blk, WG2_SMEM>>>(
        xhi, xlo, wfxhi, wfxlo, bfx, out, nullptr, nullptr, OO, DD, 3*OO, 0);
    wgemm2<true, false, true, false><<<dim3(OO/128, NN/128), blk, WG2_SMEM>>>(
        anhi, anlo, wfnhi, wfnlo, bfn, out, nullptr, nullptr, OO, DD, 3*OO, OO);
    wgemm2<true, false, true, false><<<dim3(OO/128, NN/128), blk, WG2_SMEM>>>(
        aehi, aelo, wfehi, wfelo, bfe, out, nullptr, nullptr, OO, EE, 3*OO, 2*OO);
}